// round 16
// baseline (speedup 1.0000x reference)
#include <cuda_runtime.h>

// FlowNetC correlation on GB300 — round 16: R14 (warp-autonomous pipelines,
// champion) reconfigured for 3 blocks/SM: 2-stage B+A ring (61 KB smem/block)
// + __launch_bounds__(192,3) (113-reg cap) -> 18 warps/SM of barrier-free work.
// Consumer per warp-chunk: 4 A-ldsm.x4 + 6 B-ldsm.x4 + 20 banded m16n8k8
// tf32 MMAs. Prepass: rna-tf32, parity-deinterleaved, k-contiguous scratch,
// A pre-scaled by 1/256.
//
// out[b, dy*21+dx, y, x] = (1/256) * sum_c in1[b,c,y,x] * in2[b,c, y+2dy-20, x+2dx-20]

#define DD      21
#define HH      96
#define WW      128
#define NCH     32
#define NDY     3
#define NTH     192

// per-warp region (words): B [kh2][u96][4] = 768, A [kh2][m64][4] = 512
#define WSTG    1280                 // words per stage
#define WSTG_B  (WSTG * 4)           // 5120 bytes
#define NSTG    2
#define WREG    (NSTG * WSTG)        // 2560 words per warp
#define SMEM_WORDS (6 * WREG)        // 15360 words = 61440 B per block

#define ELEMS   (8 * 256 * 96 * 128)
#define CSTEP   (2 * 96 * 2 * 64 * 4)   // +2 c4 per chunk = 98304 floats
#define KHSTEP  (96 * 2 * 64 * 4)       // +1 c4 = 49152 floats

__device__ float g1t[ELEMS];   // A scratch (in1 * 1/256, tf32 bits)
__device__ float g2t[ELEMS];   // B scratch (in2, tf32 bits)

__device__ __forceinline__ unsigned cvt_tf32(float v) {
    unsigned r;
    asm("cvt.rna.tf32.f32 %0, %1;" : "=r"(r) : "f"(v));
    return r;
}
__device__ __forceinline__ void cp16(unsigned dst, const float* src) {
    asm volatile("cp.async.cg.shared.global [%0], [%1], 16;"
                 :: "r"(dst), "l"(src));
}
__device__ __forceinline__ void ldsm4(unsigned addr, unsigned& r0, unsigned& r1,
                                      unsigned& r2, unsigned& r3) {
    asm volatile("ldmatrix.sync.aligned.m8n8.x4.shared.b16 {%0,%1,%2,%3}, [%4];"
                 : "=r"(r0), "=r"(r1), "=r"(r2), "=r"(r3) : "r"(addr));
}
__device__ __forceinline__ void mma_tf32(float (&d)[4],
                                         unsigned a0, unsigned a1,
                                         unsigned a2, unsigned a3,
                                         unsigned b0, unsigned b1) {
    asm volatile(
        "mma.sync.aligned.m16n8k8.row.col.f32.tf32.tf32.f32 "
        "{%0,%1,%2,%3}, {%4,%5,%6,%7}, {%8,%9}, {%0,%1,%2,%3};"
        : "+f"(d[0]), "+f"(d[1]), "+f"(d[2]), "+f"(d[3])
        : "r"(a0), "r"(a1), "r"(a2), "r"(a3), "r"(b0), "r"(b1));
}

// ---- prepass: cvt + transpose to [b][c4][y][par][xh][cc4] (uint4 stores) ----
__global__ void __launch_bounds__(128) prepass(const float* __restrict__ s1,
                                               const float* __restrict__ s2)
{
    const int x   = threadIdx.x;        // 0..127
    const int y   = blockIdx.x;         // 96
    const int c4  = blockIdx.y;         // 64
    const int b   = blockIdx.z & 7;
    const bool isA = blockIdx.z >= 8;
    const size_t plane = (size_t)HH * WW;
    const float* src = (isA ? s1 : s2)
        + ((size_t)(b * 256 + c4 * 4) * HH + y) * WW + x;
    const float sc = isA ? (1.0f / 256.0f) : 1.0f;   // exact, baked into A
    unsigned v0 = cvt_tf32(src[0]         * sc);
    unsigned v1 = cvt_tf32(src[plane]     * sc);
    unsigned v2 = cvt_tf32(src[2 * plane] * sc);
    unsigned v3 = cvt_tf32(src[3 * plane] * sc);
    float* dstT = isA ? g1t : g2t;
    size_t o = ((((size_t)b * 64 + c4) * HH + y) * 2 + (x & 1)) * 64 + (x >> 1);
    ((uint4*)dstT)[o] = make_uint4(v0, v1, v2, v3);
}

extern __shared__ unsigned smw[];

__global__ void __launch_bounds__(NTH, 3) corr_mma(float* __restrict__ g_out)
{
    const int b    = blockIdx.z;
    const int y    = blockIdx.y;
    const int dyg  = blockIdx.x;      // 0..6
    const int tid  = threadIdx.x;
    const int lane = tid & 31;
    const int w    = tid >> 5;        // 0..5
    const int par  = w & 1;
    const int dyl  = w >> 1;          // 0..2
    const int dy   = dyg * NDY + dyl;
    const int g    = lane >> 2;
    const int t    = lane & 3;

    const size_t plane = (size_t)HH * WW;
    const int wb = w * WREG;          // warp's smem region base (words)

    // Each warp zeros ONLY its own region (pads + OOB rows stay zero).
    for (int i = lane; i < WREG; i += 32) smw[wb + i] = 0u;
    __syncwarp();

    const unsigned sm0 = (unsigned)__cvta_generic_to_shared(smw);
    const unsigned wbB = sm0 + (unsigned)wb * 4u;     // warp base, bytes

    const int  row2 = y + 2 * dy - 20;
    const bool rok  = (row2 >= 0) && (row2 < HH);

    // ---- per-lane cp.async bases (8 copies per chunk: 4 B + 4 A) ----
    const float* bsrc = g2t + ((size_t)(((b * 64) * HH + (rok ? row2 : 0)) * 2
                                        + par) * 64 + lane) * 4;
    const unsigned bdst = wbB + (unsigned)((10 + lane) * 4) * 4u;
    const float* asrc = g1t + ((size_t)(((b * 64) * HH + y) * 2
                                        + par) * 64 + lane) * 4;
    const unsigned adst = wbB + (unsigned)(768 + lane * 4) * 4u;

    // ---- ldmatrix lane bases (bytes, stage 0 of own region) ----
    const unsigned bl_kh = (lane >> 3) & 1;
    const unsigned bl_u  = ((lane >> 4) << 3) + (lane & 7);
    const unsigned bLds  = wbB + (bl_kh * 384 + bl_u * 4) * 4u;
    const unsigned al_kh = lane >> 4;
    const unsigned al_m  = ((lane >> 3) & 1) * 8 + (lane & 7);
    const unsigned aLds  = wbB + (768 + al_kh * 256 + al_m * 4) * 4u;

    float acc[20][4];
    #pragma unroll
    for (int f = 0; f < 20; ++f)
        #pragma unroll
        for (int e = 0; e < 4; ++e) acc[f][e] = 0.0f;

    const float* bp = bsrc;
    const float* ap = asrc;
    auto issue_chunk = [&](int stg) {
        const unsigned sb = (unsigned)stg * WSTG_B;
        if (rok) {
            cp16(bdst + sb,               bp);              // kh0, u6=lane
            cp16(bdst + sb + 512,         bp + 128);        // kh0, u6=lane+32
            cp16(bdst + sb + 1536,        bp + KHSTEP);     // kh1, u6=lane
            cp16(bdst + sb + 1536 + 512,  bp + KHSTEP + 128);
        }
        bp += CSTEP;
        cp16(adst + sb,              ap);                   // kh0, m=lane
        cp16(adst + sb + 512,        ap + 128);             // kh0, m=lane+32
        cp16(adst + sb + 1024,       ap + KHSTEP);          // kh1, m=lane
        cp16(adst + sb + 1024 + 512, ap + KHSTEP + 128);
        ap += CSTEP;
    };

    // prologue: chunks 0 and 1 in flight
    issue_chunk(0); asm volatile("cp.async.commit_group;");
    issue_chunk(1); asm volatile("cp.async.commit_group;");

    for (int k = 0; k < NCH; ++k) {
        // committed groups so far = k+2; leave 1 pending -> chunk k complete
        asm volatile("cp.async.wait_group 1;");
        __syncwarp();                             // all lanes passed the wait

        const unsigned sb = (unsigned)(k & 1) * WSTG_B;

        // A fragments: 4 ldmatrix.x4 (one per m16 tile)
        unsigned a[4][4];
        #pragma unroll
        for (int mt = 0; mt < 4; ++mt)
            ldsm4(aLds + sb + mt * 256, a[mt][0], a[mt][1], a[mt][2], a[mt][3]);

        // B fragments + MMAs (j-outer, tile pair per ldsm.x4)
        #pragma unroll
        for (int jp = 0; jp < 6; ++jp) {
            unsigned b0, b1, b2, b3;
            ldsm4(bLds + sb + jp * 256, b0, b1, b2, b3);
            const int j0 = 2 * jp;
            #pragma unroll
            for (int mt = 0; mt < 4; ++mt)
                if (2 * mt <= j0 && j0 <= 2 * mt + 4)
                    mma_tf32(acc[mt * 5 + (j0 - 2 * mt)],
                             a[mt][0], a[mt][1], a[mt][2], a[mt][3], b0, b1);
            const int j1 = j0 + 1;
            if (j1 < 11) {
                #pragma unroll
                for (int mt = 0; mt < 4; ++mt)
                    if (2 * mt <= j1 && j1 <= 2 * mt + 4)
                        mma_tf32(acc[mt * 5 + (j1 - 2 * mt)],
                                 a[mt][0], a[mt][1], a[mt][2], a[mt][3], b2, b3);
            }
        }

        // refill the just-consumed stage AFTER this chunk's MMAs
        // (WAR-safe in-warp: MMA issue implies its LDSMs completed)
        if (k + 2 < NCH) issue_chunk(k & 1);
        asm volatile("cp.async.commit_group;");   // uniform group counting
    }

    // ---- epilogue: band-extract + scatter stores (1/256 pre-baked in A) ----
    float* ob = g_out + ((size_t)(b * (DD * DD) + dy * DD)) * plane
                      + (size_t)y * WW + par;
    #pragma unroll
    for (int mt = 0; mt < 4; ++mt) {
        #pragma unroll
        for (int i = 0; i < 5; ++i) {
            const int u0 = 8 * (2 * mt + i);
            const float* f = acc[mt * 5 + i];
            #pragma unroll
            for (int e = 0; e < 4; ++e) {
                int r   = (e >= 2) ? (g + 8) : g;
                int col = 2 * t + (e & 1);
                int xh  = 16 * mt + r;
                int dx  = u0 + col - xh;
                if (dx >= 0 && dx < DD)
                    ob[(size_t)dx * plane + 2 * xh] = f[e];
            }
        }
    }
}

extern "C" void kernel_launch(void* const* d_in, const int* in_sizes, int n_in,
                              void* d_out, int out_size)
{
    (void)in_sizes; (void)n_in; (void)out_size;
    const float* in1 = (const float*)d_in[0];
    const float* in2 = (const float*)d_in[1];
    float*       out = (float*)d_out;

    // kernel 1: convert + transpose both tensors into k-contiguous scratch
    prepass<<<dim3(HH, 64, 16), 128>>>(in1, in2);

    // kernel 2: banded MMA, warp-autonomous, 3 blocks/SM
    cudaFuncSetAttribute(corr_mma, cudaFuncAttributeMaxDynamicSharedMemorySize,
                         SMEM_WORDS * 4);
    dim3 grid(7, HH, 8);     // (dy-group of 3, y, b) -> 5376 blocks
    corr_mma<<<grid, NTH, SMEM_WORDS * 4>>>(out);
}

// round 17
// speedup vs baseline: 1.3772x; 1.3772x over previous
#include <cuda_runtime.h>

// FlowNetC correlation on GB300 — round 17: R14 main (champion, verbatim) +
// vectorized prepass (float4 reads, 4x fewer load instructions, identical
// output layout). Warp-autonomous cp.async 3-stage rings, ldmatrix.x4,
// banded m16n8k8 tf32 MMA.
//
// out[b, dy*21+dx, y, x] = (1/256) * sum_c in1[b,c,y,x] * in2[b,c, y+2dy-20, x+2dx-20]

#define DD      21
#define HH      96
#define WW      128
#define NCH     32
#define NDY     3
#define NTH     192

// per-warp region (words): B [kh2][u96][4] = 768, A [kh2][m64][4] = 512
#define WSTG    1280                 // words per stage
#define WSTG_B  (WSTG * 4)           // 5120 bytes
#define NSTG    3
#define WREG    (NSTG * WSTG)        // 3840 words per warp
#define SMEM_WORDS (6 * WREG)        // 23040 words = 92160 B per block

#define ELEMS   (8 * 256 * 96 * 128)
#define CSTEP   (2 * 96 * 2 * 64 * 4)   // +2 c4 per chunk = 98304 floats
#define KHSTEP  (96 * 2 * 64 * 4)       // +1 c4 = 49152 floats

__device__ float g1t[ELEMS];   // A scratch (in1 * 1/256, tf32 bits)
__device__ float g2t[ELEMS];   // B scratch (in2, tf32 bits)

__device__ __forceinline__ unsigned cvt_tf32(float v) {
    unsigned r;
    asm("cvt.rna.tf32.f32 %0, %1;" : "=r"(r) : "f"(v));
    return r;
}
__device__ __forceinline__ void cp16(unsigned dst, const float* src) {
    asm volatile("cp.async.cg.shared.global [%0], [%1], 16;"
                 :: "r"(dst), "l"(src));
}
__device__ __forceinline__ void ldsm4(unsigned addr, unsigned& r0, unsigned& r1,
                                      unsigned& r2, unsigned& r3) {
    asm volatile("ldmatrix.sync.aligned.m8n8.x4.shared.b16 {%0,%1,%2,%3}, [%4];"
                 : "=r"(r0), "=r"(r1), "=r"(r2), "=r"(r3) : "r"(addr));
}
__device__ __forceinline__ void mma_tf32(float (&d)[4],
                                         unsigned a0, unsigned a1,
                                         unsigned a2, unsigned a3,
                                         unsigned b0, unsigned b1) {
    asm volatile(
        "mma.sync.aligned.m16n8k8.row.col.f32.tf32.tf32.f32 "
        "{%0,%1,%2,%3}, {%4,%5,%6,%7}, {%8,%9}, {%0,%1,%2,%3};"
        : "+f"(d[0]), "+f"(d[1]), "+f"(d[2]), "+f"(d[3])
        : "r"(a0), "r"(a1), "r"(a2), "r"(a3), "r"(b0), "r"(b1));
}

// ---- prepass (vectorized): float4 reads along x, 4 channels per thread,
// output layout identical to R14: [b][c4][y][par][xh][cc4] uint4 words. ----
__global__ void __launch_bounds__(128) prepass(const float* __restrict__ s1,
                                               const float* __restrict__ s2)
{
    const int tid = threadIdx.x;
    const int xg  = tid & 31;           // x-group of 4 (x = 4*xg .. 4*xg+3)
    const int c4l = tid >> 5;           // 0..3
    const int y   = blockIdx.x;         // 96
    const int c4  = blockIdx.y * 4 + c4l;   // 0..63
    const int b   = blockIdx.z & 7;
    const bool isA = blockIdx.z >= 8;
    const size_t plane = (size_t)HH * WW;
    const float* src = (isA ? s1 : s2)
        + ((size_t)(b * 256 + c4 * 4) * HH + y) * WW + xg * 4;
    const float sc = isA ? (1.0f / 256.0f) : 1.0f;   // exact, baked into A

    float4 r0 = *(const float4*)(src);
    float4 r1 = *(const float4*)(src + plane);
    float4 r2 = *(const float4*)(src + 2 * plane);
    float4 r3 = *(const float4*)(src + 3 * plane);

    // word for x: (cvt(c0[x]), cvt(c1[x]), cvt(c2[x]), cvt(c3[x]))
    uint4 w0 = make_uint4(cvt_tf32(r0.x * sc), cvt_tf32(r1.x * sc),
                          cvt_tf32(r2.x * sc), cvt_tf32(r3.x * sc)); // x=4xg   par0 col 2xg
    uint4 w1 = make_uint4(cvt_tf32(r0.y * sc), cvt_tf32(r1.y * sc),
                          cvt_tf32(r2.y * sc), cvt_tf32(r3.y * sc)); // x=4xg+1 par1 col 2xg
    uint4 w2 = make_uint4(cvt_tf32(r0.z * sc), cvt_tf32(r1.z * sc),
                          cvt_tf32(r2.z * sc), cvt_tf32(r3.z * sc)); // x=4xg+2 par0 col 2xg+1
    uint4 w3 = make_uint4(cvt_tf32(r0.w * sc), cvt_tf32(r1.w * sc),
                          cvt_tf32(r2.w * sc), cvt_tf32(r3.w * sc)); // x=4xg+3 par1 col 2xg+1

    uint4* dst = (uint4*)(isA ? g1t : g2t)
        + (((size_t)b * 64 + c4) * HH + y) * 128;
    dst[2 * xg]           = w0;
    dst[2 * xg + 1]       = w2;
    dst[64 + 2 * xg]      = w1;
    dst[64 + 2 * xg + 1]  = w3;
}

extern __shared__ unsigned smw[];

__global__ void __launch_bounds__(NTH, 2) corr_mma(float* __restrict__ g_out)
{
    const int b    = blockIdx.z;
    const int y    = blockIdx.y;
    const int dyg  = blockIdx.x;      // 0..6
    const int tid  = threadIdx.x;
    const int lane = tid & 31;
    const int w    = tid >> 5;        // 0..5
    const int par  = w & 1;
    const int dyl  = w >> 1;          // 0..2
    const int dy   = dyg * NDY + dyl;
    const int g    = lane >> 2;
    const int t    = lane & 3;

    const size_t plane = (size_t)HH * WW;
    const int wb = w * WREG;          // warp's smem region base (words)

    // Each warp zeros ONLY its own region (pads + OOB rows stay zero).
    for (int i = lane; i < WREG; i += 32) smw[wb + i] = 0u;
    __syncwarp();

    const unsigned sm0 = (unsigned)__cvta_generic_to_shared(smw);
    const unsigned wbB = sm0 + (unsigned)wb * 4u;     // warp base, bytes

    const int  row2 = y + 2 * dy - 20;
    const bool rok  = (row2 >= 0) && (row2 < HH);

    // ---- per-lane cp.async bases (8 copies per chunk: 4 B + 4 A) ----
    const float* bsrc = g2t + ((size_t)(((b * 64) * HH + (rok ? row2 : 0)) * 2
                                        + par) * 64 + lane) * 4;
    const unsigned bdst = wbB + (unsigned)((10 + lane) * 4) * 4u;
    const float* asrc = g1t + ((size_t)(((b * 64) * HH + y) * 2
                                        + par) * 64 + lane) * 4;
    const unsigned adst = wbB + (unsigned)(768 + lane * 4) * 4u;

    // ---- ldmatrix lane bases (bytes, stage 0 of own region) ----
    const unsigned bl_kh = (lane >> 3) & 1;
    const unsigned bl_u  = ((lane >> 4) << 3) + (lane & 7);
    const unsigned bLds  = wbB + (bl_kh * 384 + bl_u * 4) * 4u;
    const unsigned al_kh = lane >> 4;
    const unsigned al_m  = ((lane >> 3) & 1) * 8 + (lane & 7);
    const unsigned aLds  = wbB + (768 + al_kh * 256 + al_m * 4) * 4u;

    float acc[20][4];
    #pragma unroll
    for (int f = 0; f < 20; ++f)
        #pragma unroll
        for (int e = 0; e < 4; ++e) acc[f][e] = 0.0f;

    const float* bp = bsrc;
    const float* ap = asrc;
    auto issue_chunk = [&](int stg) {
        const unsigned sb = (unsigned)stg * WSTG_B;
        if (rok) {
            cp16(bdst + sb,               bp);              // kh0, u6=lane
            cp16(bdst + sb + 512,         bp + 128);        // kh0, u6=lane+32
            cp16(bdst + sb + 1536,        bp + KHSTEP);     // kh1, u6=lane
            cp16(bdst + sb + 1536 + 512,  bp + KHSTEP + 128);
        }
        bp += CSTEP;
        cp16(adst + sb,              ap);                   // kh0, m=lane
        cp16(adst + sb + 512,        ap + 128);             // kh0, m=lane+32
        cp16(adst + sb + 1024,       ap + KHSTEP);          // kh1, m=lane
        cp16(adst + sb + 1024 + 512, ap + KHSTEP + 128);
        ap += CSTEP;
    };

    issue_chunk(0); asm volatile("cp.async.commit_group;");
    issue_chunk(1); asm volatile("cp.async.commit_group;");
    issue_chunk(2); asm volatile("cp.async.commit_group;");

    int stg = 0;
    for (int k = 0; k < NCH; ++k) {
        asm volatile("cp.async.wait_group 2;");   // own chunk-k copies done
        __syncwarp();                             // all lanes of warp passed wait

        const unsigned sb = (unsigned)stg * WSTG_B;

        // A fragments: 4 ldmatrix.x4 (one per m16 tile)
        unsigned a[4][4];
        #pragma unroll
        for (int mt = 0; mt < 4; ++mt)
            ldsm4(aLds + sb + mt * 256, a[mt][0], a[mt][1], a[mt][2], a[mt][3]);

        // B fragments + MMAs (j-outer, tile pair per ldsm.x4)
        #pragma unroll
        for (int jp = 0; jp < 6; ++jp) {
            unsigned b0, b1, b2, b3;
            ldsm4(bLds + sb + jp * 256, b0, b1, b2, b3);
            const int j0 = 2 * jp;
            #pragma unroll
            for (int mt = 0; mt < 4; ++mt)
                if (2 * mt <= j0 && j0 <= 2 * mt + 4)
                    mma_tf32(acc[mt * 5 + (j0 - 2 * mt)],
                             a[mt][0], a[mt][1], a[mt][2], a[mt][3], b0, b1);
            const int j1 = j0 + 1;
            if (j1 < 11) {
                #pragma unroll
                for (int mt = 0; mt < 4; ++mt)
                    if (2 * mt <= j1 && j1 <= 2 * mt + 4)
                        mma_tf32(acc[mt * 5 + (j1 - 2 * mt)],
                                 a[mt][0], a[mt][1], a[mt][2], a[mt][3], b2, b3);
            }
        }

        // refill freed stage AFTER this chunk's MMAs (WAR-safe: MMA issue
        // implies its LDSMs completed; asm volatile keeps textual order)
        if (k + 3 < NCH) issue_chunk(stg);
        asm volatile("cp.async.commit_group;");   // uniform group counting

        stg = (stg == 2) ? 0 : stg + 1;
    }

    // ---- epilogue: band-extract + scatter stores (1/256 pre-baked in A) ----
    float* ob = g_out + ((size_t)(b * (DD * DD) + dy * DD)) * plane
                      + (size_t)y * WW + par;
    #pragma unroll
    for (int mt = 0; mt < 4; ++mt) {
        #pragma unroll
        for (int i = 0; i < 5; ++i) {
            const int u0 = 8 * (2 * mt + i);
            const float* f = acc[mt * 5 + i];
            #pragma unroll
            for (int e = 0; e < 4; ++e) {
                int r   = (e >= 2) ? (g + 8) : g;
                int col = 2 * t + (e & 1);
                int xh  = 16 * mt + r;
                int dx  = u0 + col - xh;
                if (dx >= 0 && dx < DD)
                    ob[(size_t)dx * plane + 2 * xh] = f[e];
            }
        }
    }
}

extern "C" void kernel_launch(void* const* d_in, const int* in_sizes, int n_in,
                              void* d_out, int out_size)
{
    (void)in_sizes; (void)n_in; (void)out_size;
    const float* in1 = (const float*)d_in[0];
    const float* in2 = (const float*)d_in[1];
    float*       out = (float*)d_out;

    // kernel 1: convert + transpose both tensors into k-contiguous scratch
    prepass<<<dim3(HH, 16, 16), 128>>>(in1, in2);

    // kernel 2: banded MMA, warp-autonomous (R14 champion, verbatim)
    cudaFuncSetAttribute(corr_mma, cudaFuncAttributeMaxDynamicSharedMemorySize,
                         SMEM_WORDS * 4);
    dim3 grid(7, HH, 8);     // (dy-group of 3, y, b) -> 5376 blocks
    corr_mma<<<grid, NTH, SMEM_WORDS * 4>>>(out);
}